// round 13
// baseline (speedup 1.0000x reference)
#include <cuda_runtime.h>
#include <cstdint>

// 3D Haar DWT, level 1, x [B=2, C=32, D=64, H=128, W=128] f32
// -> out [B, 8C, D/2, H/2, W/2], subband order aaa,aad,ada,add,daa,dad,dda,ddd
// (bits: depth,height,width; channel = sb*C + c).
//
// R12: R7 smem-staged structure (compute identical to champion R1), but the
// drain phase uses the BULK-COPY ENGINE: 8x cp.async.bulk (2KB contiguous,
// shared->global) per CTA instead of warp STGs. Tests the last untested
// mechanism: SM store path vs TMA/bulk-engine write path at the DRAM
// controller. Everything else is at the measured LTS/DRAM plateau
// (74.3-75.7us, 6.4-6.5 TB/s).

#define B_   2
#define C_   32
#define D_   64
#define H_   128
#define W_   128
#define DH   (D_/2)
#define HH   (H_/2)
#define WH   (W_/2)

__device__ __forceinline__ uint32_t smem_u32(const void* p) {
    uint32_t a;
    asm("{ .reg .u64 t; cvta.to.shared.u64 t, %1; cvt.u32.u64 %0, t; }"
        : "=r"(a) : "l"(p));
    return a;
}

__global__ void __launch_bounds__(256) haar3d_kernel(
    const float* __restrict__ x, float* __restrict__ out)
{
    __shared__ __align__(128) float sm[8][8][64];   // [subband][dy_local][w] = 16 KB

    const float K = 0.35355339059327373f;  // (1/sqrt2)^3

    int tid  = threadIdx.x;
    int wq   = tid & 31;        // 0..31 : w-pair (2 output w per thread)
    int dy_l = tid >> 5;        // 0..7  : local dy row

    // cta = (((b*C + c)*DH + dz)*8 + dyb)
    int cta = blockIdx.x;
    int dyb =  cta        & 7;          // 0..7
    int dz  = (cta >> 3)  & (DH - 1);   // 0..31
    int c   = (cta >> 8)  & (C_ - 1);   // 0..31
    int b   =  cta >> 13;               // 0..1

    int dy = dyb * 8 + dy_l;            // 0..63

    // ---- phase 1: 4x LDG.128, butterfly (identical to champion) ----
    size_t ibase = ((((size_t)(b * C_ + c) * D_ + 2 * dz) * H_ + 2 * dy) * W_) + 4 * wq;
    const size_t HW = (size_t)H_ * W_;
    const float4 r00 = *(const float4*)(x + ibase);            // d0 h0
    const float4 r01 = *(const float4*)(x + ibase + W_);       // d0 h1
    const float4 r10 = *(const float4*)(x + ibase + HW);       // d1 h0
    const float4 r11 = *(const float4*)(x + ibase + HW + W_);  // d1 h1

    float wl00a = r00.x + r00.y, wh00a = r00.x - r00.y;
    float wl01a = r01.x + r01.y, wh01a = r01.x - r01.y;
    float wl10a = r10.x + r10.y, wh10a = r10.x - r10.y;
    float wl11a = r11.x + r11.y, wh11a = r11.x - r11.y;

    float wl00b = r00.z + r00.w, wh00b = r00.z - r00.w;
    float wl01b = r01.z + r01.w, wh01b = r01.z - r01.w;
    float wl10b = r10.z + r10.w, wh10b = r10.z - r10.w;
    float wl11b = r11.z + r11.w, wh11b = r11.z - r11.w;

    float s0[8], s1[8];
    {
        float hl_l0 = wl00a + wl01a, hh_l0 = wl00a - wl01a;
        float hl_h0 = wh00a + wh01a, hh_h0 = wh00a - wh01a;
        float hl_l1 = wl10a + wl11a, hh_l1 = wl10a - wl11a;
        float hl_h1 = wh10a + wh11a, hh_h1 = wh10a - wh11a;
        s0[0] = (hl_l0 + hl_l1) * K;
        s0[1] = (hl_h0 + hl_h1) * K;
        s0[2] = (hh_l0 + hh_l1) * K;
        s0[3] = (hh_h0 + hh_h1) * K;
        s0[4] = (hl_l0 - hl_l1) * K;
        s0[5] = (hl_h0 - hl_h1) * K;
        s0[6] = (hh_l0 - hh_l1) * K;
        s0[7] = (hh_h0 - hh_h1) * K;
    }
    {
        float hl_l0 = wl00b + wl01b, hh_l0 = wl00b - wl01b;
        float hl_h0 = wh00b + wh01b, hh_h0 = wh00b - wh01b;
        float hl_l1 = wl10b + wl11b, hh_l1 = wl10b - wl11b;
        float hl_h1 = wh10b + wh11b, hh_h1 = wh10b - wh11b;
        s1[0] = (hl_l0 + hl_l1) * K;
        s1[1] = (hl_h0 + hl_h1) * K;
        s1[2] = (hh_l0 + hh_l1) * K;
        s1[3] = (hh_h0 + hh_h1) * K;
        s1[4] = (hl_l0 - hl_l1) * K;
        s1[5] = (hl_h0 - hl_h1) * K;
        s1[6] = (hh_l0 - hh_l1) * K;
        s1[7] = (hh_h0 - hh_h1) * K;
    }

    // ---- stage to smem (STS.64 per subband, conflict-free) ----
#pragma unroll
    for (int sb = 0; sb < 8; sb++) {
        *(float2*)&sm[sb][dy_l][2 * wq] = make_float2(s0[sb], s1[sb]);
    }
    __syncthreads();
    // generic-proxy smem writes must be visible to the async (bulk) proxy
    asm volatile("fence.proxy.async.shared::cta;" ::: "memory");

    // ---- phase 2: threads 0..7 each issue ONE 2KB bulk store (subband=tid) ----
    if (tid < 8) {
        int sb = tid;
        // out channel = sb*C + c ; rows dyb*8..dyb*8+7 contiguous = 512 floats
        size_t obase = ((((size_t)(b * 8 * C_ + sb * C_ + c) * DH + dz) * HH + dyb * 8) * WH);
        uint32_t saddr = smem_u32(&sm[sb][0][0]);
        asm volatile(
            "cp.async.bulk.global.shared::cta.bulk_group [%0], [%1], %2;"
            :: "l"(out + obase), "r"(saddr), "n"(8 * 64 * 4) : "memory");
        asm volatile("cp.async.bulk.commit_group;" ::: "memory");
        asm volatile("cp.async.bulk.wait_group 0;" ::: "memory");
    }
    __syncthreads();
}

extern "C" void kernel_launch(void* const* d_in, const int* in_sizes, int n_in,
                              void* d_out, int out_size) {
    const float* x = (const float*)d_in[0];
    float* out = (float*)d_out;
    // grid = B*C*DH*(HH/8) = 2*32*32*8 = 16384 CTAs, 256 threads each
    haar3d_kernel<<<B_ * C_ * DH * (HH / 8), 256>>>(x, out);
}